// round 3
// baseline (speedup 1.0000x reference)
#include <cuda_runtime.h>
#include <cstdint>
#include <math.h>

#define N_ROWS 100000
#define C_CLS  20
#define D_DIM  2001
#define REG_C  0.001
// SMEM layout: W transposed, column j occupies WSTRIDE=26 words (20 used, pad
// to 26 so lane-strided LDS.64 is bank-conflict-free: 26*l mod 32 covers 16
// distinct even banks per half-warp phase).
#define WSTRIDE 26
#define SMEM_BYTES (D_DIM * WSTRIDE * 4)
#define ROWS_PER_TASK 4
#define NTASKS (N_ROWS / ROWS_PER_TASK)

__device__ double g_loss;
__device__ double g_sqsum;
__device__ int    g_y_is_i64;   // 1 if Y is int64 (read int32 view at 2*i)

// ---- packed f32x2 helpers (ptxas never emits FFMA2 from C++) ----
__device__ __forceinline__ unsigned long long pack2(float lo, float hi) {
    unsigned long long r;
    asm("mov.b64 %0, {%1,%2};" : "=l"(r) : "f"(lo), "f"(hi));
    return r;
}
__device__ __forceinline__ void unpack2(unsigned long long v, float& lo, float& hi) {
    asm("mov.b64 {%0,%1}, %2;" : "=f"(lo), "=f"(hi) : "l"(v));
}
__device__ __forceinline__ void ffma2(unsigned long long& acc, unsigned long long a,
                                      unsigned long long b) {
    asm("fma.rn.f32x2 %0, %1, %2, %0;" : "+l"(acc) : "l"(a), "l"(b));
}
__device__ __forceinline__ unsigned long long fadd2(unsigned long long a,
                                                    unsigned long long b) {
    unsigned long long r;
    asm("add.rn.f32x2 %0, %1, %2;" : "=l"(r) : "l"(a), "l"(b));
    return r;
}

// Init accumulators AND probe Y's element width. If Y is int64 (little-endian),
// the int32 view is [label,0,label,0,...]; 128 consecutive odd positions all
// zero is impossible (p ~ 20^-128) for genuine int32 labels drawn from [0,20).
__global__ void init_kernel(const int* __restrict__ y32) {
    g_loss  = 0.0;
    g_sqsum = 0.0;
    int allz = 1;
    for (int i = 0; i < 128; i++)
        if (y32[2 * i + 1] != 0) { allz = 0; break; }
    g_y_is_i64 = allz;
}

// Frobenius-norm-squared of init_weights (40020 floats)
__global__ void sqsum_kernel(const float* __restrict__ iw, int n) {
    float s = 0.0f;
    for (int i = blockIdx.x * blockDim.x + threadIdx.x; i < n; i += gridDim.x * blockDim.x) {
        float v = iw[i];
        s = fmaf(v, v, s);
    }
    #pragma unroll
    for (int o = 16; o > 0; o >>= 1) s += __shfl_xor_sync(0xffffffffu, s, o);
    if ((threadIdx.x & 31) == 0) atomicAdd(&g_sqsum, (double)s);
}

// Main: per-row scores (X @ W^T), picked + logsumexp(-scores), summed into g_loss.
// One warp processes ROWS_PER_TASK rows per task; lanes stride over D.
__global__ void __launch_bounds__(256, 1)
loss_kernel(const float* __restrict__ W, const float* __restrict__ X,
            const int* __restrict__ Y) {
    extern __shared__ float ws[];

    // Load W [C,D] into SMEM transposed: ws[j*WSTRIDE + c]
    for (int idx = threadIdx.x; idx < C_CLS * D_DIM; idx += blockDim.x) {
        int c = idx / D_DIM;
        int j = idx - c * D_DIM;
        ws[j * WSTRIDE + c] = W[idx];
    }
    __syncthreads();

    const unsigned long long* wp = (const unsigned long long*)ws;  // pairs: j*13 + k

    const int lane   = threadIdx.x & 31;
    const int warp   = threadIdx.x >> 5;
    const int gw     = blockIdx.x * (blockDim.x >> 5) + warp;
    const int nwarps = gridDim.x * (blockDim.x >> 5);
    const int ymul   = g_y_is_i64 ? 2 : 1;   // int64 labels: low word at 2*i

    double wsum = 0.0;

    for (int task = gw; task < NTASKS; task += nwarps) {
        const int r0 = task * ROWS_PER_TASK;
        const float* x0 = X + (size_t)r0 * D_DIM;

        unsigned long long acc[ROWS_PER_TASK][10];
        #pragma unroll
        for (int r = 0; r < ROWS_PER_TASK; r++)
            #pragma unroll
            for (int k = 0; k < 10; k++) acc[r][k] = 0ull;

        #pragma unroll 2
        for (int j = lane; j < D_DIM; j += 32) {
            // global loads first (front-batch for MLP)
            float x[ROWS_PER_TASK];
            #pragma unroll
            for (int r = 0; r < ROWS_PER_TASK; r++)
                x[r] = __ldg(x0 + r * D_DIM + j);

            unsigned long long w[10];
            const unsigned long long* wr = wp + j * 13;
            #pragma unroll
            for (int k = 0; k < 10; k++) w[k] = wr[k];

            #pragma unroll
            for (int r = 0; r < ROWS_PER_TASK; r++) {
                unsigned long long xx = pack2(x[r], x[r]);
                #pragma unroll
                for (int k = 0; k < 10; k++) ffma2(acc[r][k], xx, w[k]);
            }
        }

        // butterfly all-reduce across lanes (packed adds)
        #pragma unroll
        for (int r = 0; r < ROWS_PER_TASK; r++) {
            #pragma unroll
            for (int k = 0; k < 10; k++) {
                unsigned long long v = acc[r][k];
                #pragma unroll
                for (int o = 16; o > 0; o >>= 1)
                    v = fadd2(v, __shfl_xor_sync(0xffffffffu, v, o));
                acc[r][k] = v;
            }
        }

        // lanes 0..3 compute the per-row loss for rows r0..r0+3
        float myloss = 0.0f;
        #pragma unroll
        for (int r = 0; r < ROWS_PER_TASK; r++) {
            if (lane == r) {
                float s[C_CLS];
                #pragma unroll
                for (int k = 0; k < 10; k++) unpack2(acc[r][k], s[2 * k], s[2 * k + 1]);
                const int y = Y[(r0 + r) * ymul];
                float picked = 0.0f;
                float m = -s[0];
                #pragma unroll
                for (int c = 0; c < C_CLS; c++) {
                    if (c == y) picked = s[c];
                    m = fmaxf(m, -s[c]);
                }
                float sum = 0.0f;
                #pragma unroll
                for (int c = 0; c < C_CLS; c++) sum += __expf(-s[c] - m);
                myloss = picked + m + __logf(sum);
            }
        }
        myloss += __shfl_down_sync(0xffffffffu, myloss, 2);
        myloss += __shfl_down_sync(0xffffffffu, myloss, 1);
        if (lane == 0) wsum += (double)myloss;
    }

    if (lane == 0) atomicAdd(&g_loss, wsum);
}

__global__ void fin_kernel(float* out) {
    out[0] = (float)(g_loss / (double)N_ROWS + REG_C * sqrt(g_sqsum));
}

extern "C" void kernel_launch(void* const* d_in, const int* in_sizes, int n_in,
                              void* d_out, int out_size) {
    const float* W  = (const float*)d_in[0];  // weights [C, D]
    const float* X  = (const float*)d_in[1];  // X [N, D]
    const int*   Y  = (const int*)d_in[2];    // Y [N] (int32 or int64, probed)
    const float* IW = (const float*)d_in[3];  // init_weights [C, D]
    float* out = (float*)d_out;

    int sms = 148;
    cudaDeviceGetAttribute(&sms, cudaDevAttrMultiProcessorCount, 0);

    cudaFuncSetAttribute(loss_kernel, cudaFuncAttributeMaxDynamicSharedMemorySize,
                         SMEM_BYTES);

    init_kernel<<<1, 1>>>(Y);
    sqsum_kernel<<<64, 256>>>(IW, C_CLS * D_DIM);
    loss_kernel<<<sms, 256, SMEM_BYTES>>>(W, X, Y);
    fin_kernel<<<1, 1>>>(out);
}

// round 4
// speedup vs baseline: 1.1941x; 1.1941x over previous
#include <cuda_runtime.h>
#include <cstdint>
#include <math.h>

#define N_ROWS 100000
#define C_CLS  20
#define D_DIM  2001
#define REG_C  0.001
// SMEM layout: W transposed, column j occupies WSTRIDE=28 words (20 used, pad
// to 28 so each row is 112 B => 16B-aligned (LDS.128 legal) and conflict-free:
// per 8-lane phase, 28*l mod 32 = {0,28,24,20,16,12,8,4} -> disjoint 4-word
// groups covering all 32 banks.
#define WSTRIDE 28
#define SMEM_BYTES (D_DIM * WSTRIDE * 4)
#define ROWS_PER_TASK 4
#define NTASKS (N_ROWS / ROWS_PER_TASK)
#define TPB 512

__device__ double g_loss;
__device__ double g_sqsum;
__device__ int    g_y_is_i64;   // 1 if Y is int64 (read int32 view at 2*i)

// ---- packed f32x2 helpers (ptxas never emits FFMA2 from C++) ----
__device__ __forceinline__ unsigned long long pack2(float lo, float hi) {
    unsigned long long r;
    asm("mov.b64 %0, {%1,%2};" : "=l"(r) : "f"(lo), "f"(hi));
    return r;
}
__device__ __forceinline__ void unpack2(unsigned long long v, float& lo, float& hi) {
    asm("mov.b64 {%0,%1}, %2;" : "=f"(lo), "=f"(hi) : "l"(v));
}
__device__ __forceinline__ void ffma2(unsigned long long& acc, unsigned long long a,
                                      unsigned long long b) {
    asm("fma.rn.f32x2 %0, %1, %2, %0;" : "+l"(acc) : "l"(a), "l"(b));
}
__device__ __forceinline__ unsigned long long fadd2(unsigned long long a,
                                                    unsigned long long b) {
    unsigned long long r;
    asm("add.rn.f32x2 %0, %1, %2;" : "=l"(r) : "l"(a), "l"(b));
    return r;
}

// Init accumulators AND probe Y's element width (PARALLEL — the serial version
// cost ~50+us of dependent single-thread LDGs). If Y is int64 little-endian,
// the int32 view is [label,0,label,0,...]; 128 odd positions all zero is
// impossible (p ~ 20^-128) for genuine int32 labels from [0,20).
__global__ void init_kernel(const int* __restrict__ y32) {
    int nz = 0;
    for (int i = threadIdx.x; i < 128; i += 32)
        if (y32[2 * i + 1] != 0) nz = 1;
    unsigned any = __ballot_sync(0xffffffffu, nz);
    if (threadIdx.x == 0) {
        g_loss  = 0.0;
        g_sqsum = 0.0;
        g_y_is_i64 = (any == 0u);
    }
}

// Frobenius-norm-squared of init_weights (40020 floats)
__global__ void sqsum_kernel(const float* __restrict__ iw, int n) {
    float s = 0.0f;
    for (int i = blockIdx.x * blockDim.x + threadIdx.x; i < n; i += gridDim.x * blockDim.x) {
        float v = iw[i];
        s = fmaf(v, v, s);
    }
    #pragma unroll
    for (int o = 16; o > 0; o >>= 1) s += __shfl_xor_sync(0xffffffffu, s, o);
    if ((threadIdx.x & 31) == 0) atomicAdd(&g_sqsum, (double)s);
}

// Main: per-row scores (X @ W^T), picked + logsumexp(-scores), summed into g_loss.
// One warp processes ROWS_PER_TASK rows per task; lanes stride over D.
// 512 threads/CTA (16 warps/SM, 4/SMSP) + x-prefetch one iteration ahead.
__global__ void __launch_bounds__(TPB, 1)
loss_kernel(const float* __restrict__ W, const float* __restrict__ X,
            const int* __restrict__ Y) {
    extern __shared__ float ws[];

    // Load W [C,D] into SMEM transposed: ws[j*WSTRIDE + c]
    for (int idx = threadIdx.x; idx < C_CLS * D_DIM; idx += blockDim.x) {
        int c = idx / D_DIM;
        int j = idx - c * D_DIM;
        ws[j * WSTRIDE + c] = W[idx];
    }
    __syncthreads();

    const ulonglong2* wp = (const ulonglong2*)ws;  // 16B chunks: j*7 + k

    const int lane   = threadIdx.x & 31;
    const int warp   = threadIdx.x >> 5;
    const int gw     = blockIdx.x * (blockDim.x >> 5) + warp;
    const int nwarps = gridDim.x * (blockDim.x >> 5);
    const int ymul   = g_y_is_i64 ? 2 : 1;   // int64 labels: low word at 2*i

    double wsum = 0.0;

    for (int task = gw; task < NTASKS; task += nwarps) {
        const int r0 = task * ROWS_PER_TASK;
        const float* x0 = X + (size_t)r0 * D_DIM;

        unsigned long long acc[ROWS_PER_TASK][10];
        #pragma unroll
        for (int r = 0; r < ROWS_PER_TASK; r++)
            #pragma unroll
            for (int k = 0; k < 10; k++) acc[r][k] = 0ull;

        // prefetch first x column
        float xn[ROWS_PER_TASK];
        #pragma unroll
        for (int r = 0; r < ROWS_PER_TASK; r++)
            xn[r] = __ldg(x0 + r * D_DIM + lane);

        for (int j = lane; j < D_DIM; j += 32) {
            float x[ROWS_PER_TASK];
            #pragma unroll
            for (int r = 0; r < ROWS_PER_TASK; r++) x[r] = xn[r];

            // prefetch next iteration's x (predicated; lands ~full iter early)
            const int jn = j + 32;
            if (jn < D_DIM) {
                #pragma unroll
                for (int r = 0; r < ROWS_PER_TASK; r++)
                    xn[r] = __ldg(x0 + r * D_DIM + jn);
            }

            // 20 W floats for this j: 5x LDS.128, conflict-free
            ulonglong2 w[5];
            const ulonglong2* wr = wp + j * 7;
            #pragma unroll
            for (int k = 0; k < 5; k++) w[k] = wr[k];

            #pragma unroll
            for (int r = 0; r < ROWS_PER_TASK; r++) {
                unsigned long long xx = pack2(x[r], x[r]);
                #pragma unroll
                for (int k = 0; k < 5; k++) {
                    ffma2(acc[r][2 * k],     xx, w[k].x);
                    ffma2(acc[r][2 * k + 1], xx, w[k].y);
                }
            }
        }

        // butterfly all-reduce across lanes (packed adds)
        #pragma unroll
        for (int r = 0; r < ROWS_PER_TASK; r++) {
            #pragma unroll
            for (int k = 0; k < 10; k++) {
                unsigned long long v = acc[r][k];
                #pragma unroll
                for (int o = 16; o > 0; o >>= 1)
                    v = fadd2(v, __shfl_xor_sync(0xffffffffu, v, o));
                acc[r][k] = v;
            }
        }

        // lanes 0..3 compute the per-row loss for rows r0..r0+3
        float myloss = 0.0f;
        #pragma unroll
        for (int r = 0; r < ROWS_PER_TASK; r++) {
            if (lane == r) {
                float s[C_CLS];
                #pragma unroll
                for (int k = 0; k < 10; k++) unpack2(acc[r][k], s[2 * k], s[2 * k + 1]);
                const int y = Y[(r0 + r) * ymul];
                float picked = 0.0f;
                float m = -s[0];
                #pragma unroll
                for (int c = 0; c < C_CLS; c++) {
                    if (c == y) picked = s[c];
                    m = fmaxf(m, -s[c]);
                }
                float sum = 0.0f;
                #pragma unroll
                for (int c = 0; c < C_CLS; c++) sum += __expf(-s[c] - m);
                myloss = picked + m + __logf(sum);
            }
        }
        myloss += __shfl_down_sync(0xffffffffu, myloss, 2);
        myloss += __shfl_down_sync(0xffffffffu, myloss, 1);
        if (lane == 0) wsum += (double)myloss;
    }

    if (lane == 0) atomicAdd(&g_loss, wsum);
}

__global__ void fin_kernel(float* out) {
    out[0] = (float)(g_loss / (double)N_ROWS + REG_C * sqrt(g_sqsum));
}

extern "C" void kernel_launch(void* const* d_in, const int* in_sizes, int n_in,
                              void* d_out, int out_size) {
    const float* W  = (const float*)d_in[0];  // weights [C, D]
    const float* X  = (const float*)d_in[1];  // X [N, D]
    const int*   Y  = (const int*)d_in[2];    // Y [N] (int32 or int64, probed)
    const float* IW = (const float*)d_in[3];  // init_weights [C, D]
    float* out = (float*)d_out;

    int sms = 148;
    cudaDeviceGetAttribute(&sms, cudaDevAttrMultiProcessorCount, 0);

    cudaFuncSetAttribute(loss_kernel, cudaFuncAttributeMaxDynamicSharedMemorySize,
                         SMEM_BYTES);

    init_kernel<<<1, 32>>>(Y);
    sqsum_kernel<<<64, 256>>>(IW, C_CLS * D_DIM);
    loss_kernel<<<sms, TPB, SMEM_BYTES>>>(W, X, Y);
    fin_kernel<<<1, 1>>>(out);
}